// round 15
// baseline (speedup 1.0000x reference)
#include <cuda_runtime.h>
#include <cuda_bf16.h>
#include <math.h>

// Problem constants
#define HH    16
#define WW    16
#define DD    6
#define EMBD  32
#define CELLD 128
#define BB    32
#define NN    8
#define BND   256           // B*N
#define QQ    1536          // D*H*W
#define KKEY  256           // H*W
#define TQ    64            // q rows per block
#define NTHR  256

typedef unsigned long long u64;

// packed dual-FMA (FFMA2)
#define FMA2(d, a, b, c) \
    asm("fma.rn.f32x2 %0, %1, %2, %3;" : "=l"(d) : "l"(a), "l"(b), "l"(c))

__device__ __forceinline__ float u2lo(u64 u) { return __uint_as_float((unsigned)(u & 0xffffffffu)); }
__device__ __forceinline__ float u2hi(u64 u) { return __uint_as_float((unsigned)(u >> 32)); }
__device__ __forceinline__ float u2sum(u64 u) { return u2lo(u) + u2hi(u); }

struct F4U { union { float4 f; u64 u[2]; }; };

// warp mma: D(f32 4regs) += A(bf16 4regs) * B(bf16 2regs), m16n8k16
#define MMA16816(d, a, b0, b1) \
    asm volatile("mma.sync.aligned.m16n8k16.row.col.f32.bf16.bf16.f32 " \
        "{%0,%1,%2,%3}, {%4,%5,%6,%7}, {%8,%9}, {%0,%1,%2,%3};" \
        : "+f"((d)[0]), "+f"((d)[1]), "+f"((d)[2]), "+f"((d)[3]) \
        : "r"((a)[0]), "r"((a)[1]), "r"((a)[2]), "r"((a)[3]), "r"(b0), "r"(b1))

__device__ __forceinline__ unsigned pack_bf16x2(float f0, float f1) {
    unsigned r;
    asm("cvt.rn.bf16x2.f32 %0, %1, %2;" : "=r"(r) : "f"(f1), "f"(f0));
    return r;
}

__device__ __forceinline__ void split2(float f0, float f1, unsigned& uh, unsigned& ul) {
    uh = pack_bf16x2(f0, f1);
    float h0 = __uint_as_float(uh << 16);
    float h1 = __uint_as_float(uh & 0xffff0000u);
    ul = pack_bf16x2(f0 - h0, f1 - h1);
}

// ---- scratch (device globals; no allocations allowed) ----
__device__ float g_pose_trans[BND * 12];
__device__ __align__(16) float g_embo[KKEY * EMBD];
__device__ __align__(16) unsigned g_vhi[BND * 128 * 128];   // V split-bf16 hi, [bn][c][kpair]
__device__ __align__(16) unsigned g_vlo[BND * 128 * 128];   // V split-bf16 lo

__device__ __forceinline__ float lin16(int i) { return -1.0f + (2.0f / 15.0f) * (float)i; }

__device__ __forceinline__ void mat2quat7(const float* m, float* out7) {
    float m00 = m[0], m01 = m[1], m02 = m[2], tx = m[3];
    float m10 = m[4], m11 = m[5], m12 = m[6], ty = m[7];
    float m20 = m[8], m21 = m[9], m22 = m[10], tz = m[11];
    float t, q0, q1, q2, q3;
    if (m22 < 0.0f) {
        if (m00 > m11) {
            t = 1.0f + m00 - m11 - m22;
            q0 = t; q1 = m01 + m10; q2 = m20 + m02; q3 = m12 - m21;
        } else {
            t = 1.0f - m00 + m11 - m22;
            q0 = m01 + m10; q1 = t; q2 = m12 + m21; q3 = m20 - m02;
        }
    } else {
        if (m00 < -m11) {
            t = 1.0f - m00 - m11 + m22;
            q0 = m20 + m02; q1 = m12 + m21; q2 = t; q3 = m01 - m10;
        } else {
            t = 1.0f + m00 + m11 + m22;
            q0 = m12 - m21; q1 = m20 - m02; q2 = m01 - m10; q3 = t;
        }
    }
    float s = 0.5f / sqrtf(t);
    out7[0] = tx; out7[1] = ty; out7[2] = tz;
    out7[3] = q0 * s; out7[4] = q1 * s; out7[5] = q2 * s; out7[6] = q3 * s;
}

// =================== Kernel A: poses + key embeddings ===================
__global__ void kA(const float* __restrict__ pose_o, const float* __restrict__ pose_q,
                   const float* __restrict__ Wk1, const float* __restrict__ bk1,
                   const float* __restrict__ Wk2, const float* __restrict__ bk2,
                   float* __restrict__ out_poq, float* __restrict__ out_pqq)
{
    int t = threadIdx.x;  // 256 threads, 1 block

    {
        float q7[7];
        mat2quat7(pose_o + t * 12, q7);
#pragma unroll
        for (int i = 0; i < 7; i++) out_poq[t * 7 + i] = q7[i];
    }
    if (t < BB) {
        float q7[7];
        mat2quat7(pose_q + t * 12, q7);
#pragma unroll
        for (int i = 0; i < 7; i++) out_pqq[t * 7 + i] = q7[i];
    }

    // relative pose: inv([Ro|to]) @ [Rq|tq]  (fp64 adjugate inverse)
    {
        const float* po = pose_o + t * 12;
        const float* pq = pose_q + (t >> 3) * 12;
        double a[3][3], to[3], Rq[3][3], tq[3];
#pragma unroll
        for (int i = 0; i < 3; i++) {
#pragma unroll
            for (int j = 0; j < 3; j++) { a[i][j] = po[i * 4 + j]; Rq[i][j] = pq[i * 4 + j]; }
            to[i] = po[i * 4 + 3]; tq[i] = pq[i * 4 + 3];
        }
        double c00 = a[1][1] * a[2][2] - a[1][2] * a[2][1];
        double c01 = a[1][2] * a[2][0] - a[1][0] * a[2][2];
        double c02 = a[1][0] * a[2][1] - a[1][1] * a[2][0];
        double det = a[0][0] * c00 + a[0][1] * c01 + a[0][2] * c02;
        double inv[3][3];
        inv[0][0] = c00 / det;
        inv[1][0] = c01 / det;
        inv[2][0] = c02 / det;
        inv[0][1] = (a[0][2] * a[2][1] - a[0][1] * a[2][2]) / det;
        inv[1][1] = (a[0][0] * a[2][2] - a[0][2] * a[2][0]) / det;
        inv[2][1] = (a[0][1] * a[2][0] - a[0][0] * a[2][1]) / det;
        inv[0][2] = (a[0][1] * a[1][2] - a[0][2] * a[1][1]) / det;
        inv[1][2] = (a[0][2] * a[1][0] - a[0][0] * a[1][2]) / det;
        inv[2][2] = (a[0][0] * a[1][1] - a[0][1] * a[1][0]) / det;
#pragma unroll
        for (int i = 0; i < 3; i++) {
#pragma unroll
            for (int j = 0; j < 3; j++) {
                double s = 0.0;
#pragma unroll
                for (int k = 0; k < 3; k++) s += inv[i][k] * Rq[k][j];
                g_pose_trans[t * 12 + i * 4 + j] = (float)s;
            }
            double s = 0.0;
#pragma unroll
            for (int k = 0; k < 3; k++) s += inv[i][k] * (tq[k] - to[k]);
            g_pose_trans[t * 12 + i * 4 + 3] = (float)s;
        }
    }

    // key embeddings: 2 -> 128 relu -> 32, one key per thread
    {
        float c0 = lin16(t >> 4), c1 = lin16(t & 15);
        float h[128];
#pragma unroll
        for (int j = 0; j < 128; j++) {
            float v = fmaf(c0, Wk1[j], fmaf(c1, Wk1[128 + j], bk1[j]));
            h[j] = fmaxf(v, 0.0f);
        }
#pragma unroll 4
        for (int e = 0; e < EMBD; e++) {
            float s = bk2[e];
#pragma unroll
            for (int j = 0; j < 128; j++) s = fmaf(h[j], Wk2[j * EMBD + e], s);
            g_embo[t * EMBD + e] = s;
        }
    }
}

// =================== Kernel A2: V fp32 -> split-bf16 precompute ===================
__global__ void kA2(const float* __restrict__ vc)
{
    const int bn = blockIdx.x;          // 0..255
    const int t  = threadIdx.x;         // 0..255
    const float* src = vc + (size_t)bn * 32768;
    unsigned* dh = g_vhi + (size_t)bn * 16384;
    unsigned* dl = g_vlo + (size_t)bn * 16384;
#pragma unroll
    for (int it = 0; it < 32; it++) {
        int idx = t + it * 256;         // 0..8191
        int c = idx >> 6, f = idx & 63;
        float4 v = *(const float4*)(src + c * 256 + f * 4);
        unsigned h0, l0, h1, l1;
        split2(v.x, v.y, h0, l0);
        split2(v.z, v.w, h1, l1);
        *(uint2*)&dh[c * 128 + f * 2] = make_uint2(h0, h1);
        *(uint2*)&dl[c * 128 + f * 2] = make_uint2(l0, l1);
    }
}

// =================== Kernel B: fused main (256 thr, TQ=64, mma, low-sync) ===================
#define PATT  260   // att [64][260] fp32
#define POUT  66    // epilogue staging [128][66] (att-region union)
#define PV    68    // V half bf16 pitch (words, 128 k values = 64 data words)
#define PBH   132   // hid bf16 pitch (words)
#define PAF   132   // full-row att bf16 pitch (words)
#define PBE   20    // e-dim bf16 fragment pitch (words)

#define OFF_WQ2H  0                           // 4224
#define OFF_WQ2L  4224                        // 4224
#define OFF_EOH   8448                        // 5120
#define OFF_EOL   13568                       // 5120
#define OFF_WA1H  18688                       // 1280
#define OFF_WA1L  19968                       // 1280
#define OFF_ATT   21248                       // 17408: unions att fp32 / out / V-half bf16
#define OFF_TILE  38656                       // 16896: unions hid+eq / att bf16 full-row
#define OFF_BQ2   55552                       // 32
#define OFF_WA2   55584                       // 64
#define OFF_BA1   55648                       // 64
#define OFF_MASKA 55712                       // 64 (half-0 mask partials)
#define OFF_MASKB 55776                       // 64 (half-1 mask partials)
#define OFF_POSE  55840                       // 96
#define OFF_CODE  55936                       // 192
#define SMEM_FLOATS 56128
#define SMEM_BYTES  (SMEM_FLOATS * 4)

extern __shared__ float sm[];

__global__ void __launch_bounds__(NTHR, 1)
kB(const float* __restrict__ Wq1, const float* __restrict__ bq1,
   const float* __restrict__ Wq2, const float* __restrict__ bq2,
   const float* __restrict__ Wa1, const float* __restrict__ ba1,
   const float* __restrict__ Wa2, const float* __restrict__ ba2,
   float* __restrict__ dout)
{
    const int t  = threadIdx.x;          // 0..255
    const int qt = blockIdx.x;           // 0..23
    const int b  = blockIdx.y;           // 0..31

    float* sAtt  = sm + OFF_ATT;   // fp32 logits (stage 4 -> softmax)
    float* sOut  = sm + OFF_ATT;   // union (epilogue)
    float* sbq2  = sm + OFF_BQ2;
    float* sWa2  = sm + OFF_WA2;
    float* sba1  = sm + OFF_BA1;
    float* sMWa  = sm + OFF_MASKA;
    float* sMWb  = sm + OFF_MASKB;
    float* sPose = sm + OFF_POSE;
    float* sCode = sm + OFF_CODE;
    unsigned* wq2H = (unsigned*)(sm + OFF_WQ2H);  // [32 e][132] words
    unsigned* wq2L = (unsigned*)(sm + OFF_WQ2L);
    unsigned* eoH  = (unsigned*)(sm + OFF_EOH);   // [256 k][20] words
    unsigned* eoL  = (unsigned*)(sm + OFF_EOL);
    unsigned* wa1H = (unsigned*)(sm + OFF_WA1H);  // [64 j][20] words
    unsigned* wa1L = (unsigned*)(sm + OFF_WA1L);
    unsigned* hidH = (unsigned*)(sm + OFF_TILE);            // [64 q][132]
    unsigned* hidL = (unsigned*)(sm + OFF_TILE + 8448);
    unsigned* eqH  = (unsigned*)(sm + OFF_TILE + 13824);    // [64 q][20]
    unsigned* eqL  = (unsigned*)(sm + OFF_TILE + 15104);
    unsigned* ahiF = (unsigned*)(sm + OFF_TILE);            // [64 q][132] full-row att bf16
    unsigned* aloF = (unsigned*)(sm + OFF_TILE + 8448);
    unsigned* vhiW = (unsigned*)(sm + OFF_ATT);             // [128 c][68] V half bf16
    unsigned* vloW = (unsigned*)(sm + OFF_ATT + 8704);

    unsigned sb_u32;
    asm("{ .reg .u64 tmp; cvta.to.shared.u64 tmp, %1; cvt.u32.u64 %0, tmp; }"
        : "=r"(sb_u32) : "l"(sm));

    // ---- one-time loads / conversions ----
    // Wq2 [256 h][32 e] -> split-bf16 K-major tiles [32 e][128 hpair words]
    {
        const int e = t >> 3;
        const int hp0 = (t & 7) * 16;
#pragma unroll
        for (int i = 0; i < 16; i++) {
            int hp = hp0 + i;
            float f0 = Wq2[(2 * hp) * 32 + e];
            float f1 = Wq2[(2 * hp + 1) * 32 + e];
            unsigned uh, ul;
            split2(f0, f1, uh, ul);
            wq2H[e * PBH + hp] = uh;
            wq2L[e * PBH + hp] = ul;
        }
    }
    // embO [256 k][32 e] fp32 -> split-bf16 [k][16 ewords]
    {
        const float* ep = g_embo + t * 32;
#pragma unroll
        for (int w = 0; w < 16; w++) {
            unsigned uh, ul;
            split2(ep[2 * w], ep[2 * w + 1], uh, ul);
            eoH[t * PBE + w] = uh;
            eoL[t * PBE + w] = ul;
        }
    }
    // Wa1 [32 e][64 j] -> split-bf16 transposed [j][16 ewords]
    if (t < 64) {
#pragma unroll
        for (int w = 0; w < 16; w++) {
            float f0 = Wa1[(2 * w) * 64 + t];
            float f1 = Wa1[(2 * w + 1) * 64 + t];
            unsigned uh, ul;
            split2(f0, f1, uh, ul);
            wa1H[t * PBE + w] = uh;
            wa1L[t * PBE + w] = ul;
        }
    }
    if (t < 64) { sWa2[t] = Wa2[t]; sba1[t] = ba1[t]; }
    if (t < 32) sbq2[t] = bq2[t];
    if (t < 96) sPose[t] = g_pose_trans[b * 96 + t];
    if (t < TQ) {
        int q = qt * TQ + t;
        int d = q >> 8, rm = q & 255;
        sCode[t * 3 + 0] = 0.2f * (float)d;
        sCode[t * 3 + 1] = lin16(rm >> 4);
        sCode[t * 3 + 2] = lin16(rm & 15);
    }

    // stage-1 per-thread weights: two adjacent Wq1 columns (h = 2hp, 2hp+1)
    const int hp   = t & 127;
    const int r0s1 = (t >> 7) * 32;      // rows [r0s1, r0s1+32)
    float wqa[15], wqb[15];
#pragma unroll
    for (int i = 0; i < 15; i++) {
        wqa[i] = Wq1[i * 256 + 2 * hp];
        wqb[i] = Wq1[i * 256 + 2 * hp + 1];
    }
    const float wba = bq1[2 * hp], wbb = bq1[2 * hp + 1];
    const float ba2v = ba2[0];

    // mma tiling: 8 warps = 4 m-tiles x 2 halves
    const int wid = t >> 5, lane = t & 31;
    const int fg  = lane >> 2, fth = lane & 3;       // fragment coords
    const int mrow = (wid >> 1) * 16 + fg;           // q row base
    const int half = wid & 1;
    const int cb   = half * 64;                      // stage-6 c half
    const int nb2  = half * 16;                      // stage-2 e half

    float acc[8][4];
#pragma unroll
    for (int i = 0; i < 8; i++)
#pragma unroll
        for (int j = 0; j < 4; j++) acc[i][j] = 0.0f;

    __syncthreads();

    for (int n = 0; n < NN; n++) {
        const int bn = b * NN + n;
        const size_t vbase = (size_t)bn * 16384;

        // ---- stage 1: hidden = relu(inp @ Wq1 + b), written as split-bf16 ----
        {
            const float* ps = &sPose[n * 12];
            float basea = wba, baseb = wbb;
#pragma unroll
            for (int i = 0; i < 12; i++) {
                basea = fmaf(ps[i], wqa[i], basea);
                baseb = fmaf(ps[i], wqb[i], baseb);
            }
#pragma unroll 4
            for (int rr = 0; rr < 32; rr++) {
                const int r = r0s1 + rr;
                float c0 = sCode[r * 3 + 0], c1 = sCode[r * 3 + 1], c2 = sCode[r * 3 + 2];
                float va = basea, vb = baseb;
                va = fmaf(c0, wqa[12], va); vb = fmaf(c0, wqb[12], vb);
                va = fmaf(c1, wqa[13], va); vb = fmaf(c1, wqb[13], vb);
                va = fmaf(c2, wqa[14], va); vb = fmaf(c2, wqb[14], vb);
                va = fmaxf(va, 0.0f); vb = fmaxf(vb, 0.0f);
                unsigned uh, ul;
                split2(va, vb, uh, ul);
                hidH[r * PBH + hp] = uh;
                hidL[r * PBH + hp] = ul;
            }
        }
        __syncthreads();                                        // (1)

        // ---- stage 2 (mma): embq = hid @ Wq2 + b -> split-bf16 fragments ----
        {
            float ea[2][4];
#pragma unroll
            for (int i = 0; i < 2; i++)
#pragma unroll
                for (int j = 0; j < 4; j++) ea[i][j] = 0.0f;
#pragma unroll
            for (int ks = 0; ks < 16; ks++) {
                const int wA = mrow * PBH + ks * 8 + fth;
                unsigned ah[4], al[4];
                ah[0] = hidH[wA];          ah[1] = hidH[wA + 8 * PBH];
                ah[2] = hidH[wA + 4];      ah[3] = hidH[wA + 8 * PBH + 4];
                al[0] = hidL[wA];          al[1] = hidL[wA + 8 * PBH];
                al[2] = hidL[wA + 4];      al[3] = hidL[wA + 8 * PBH + 4];
#pragma unroll
                for (int nt = 0; nt < 2; nt++) {
                    const int wB = (nb2 + nt * 8 + fg) * PBH + ks * 8 + fth;
                    unsigned bh0 = wq2H[wB], bh1 = wq2H[wB + 4];
                    MMA16816(ea[nt], ah, bh0, bh1);
                    MMA16816(ea[nt], al, bh0, bh1);
                    unsigned bl0 = wq2L[wB], bl1 = wq2L[wB + 4];
                    MMA16816(ea[nt], ah, bl0, bl1);
                }
            }
            __syncthreads();                                    // (2) hid reads done
#pragma unroll
            for (int nt = 0; nt < 2; nt++) {
                const int e0 = nb2 + nt * 8 + 2 * fth;
                unsigned uh, ul;
                split2(ea[nt][0] + sbq2[e0], ea[nt][1] + sbq2[e0 + 1], uh, ul);
                eqH[mrow * PBE + (e0 >> 1)] = uh;
                eqL[mrow * PBE + (e0 >> 1)] = ul;
                split2(ea[nt][2] + sbq2[e0], ea[nt][3] + sbq2[e0 + 1], uh, ul);
                eqH[(mrow + 8) * PBE + (e0 >> 1)] = uh;
                eqL[(mrow + 8) * PBE + (e0 >> 1)] = ul;
            }
        }
        __syncthreads();                                        // (3)

        // ---- stage 3 (mma, in-register): mask partials = relu(embq@Wa1+ba1)@Wa2 ----
        {
            const int jb = half * 32;
            float aa[4][4];
#pragma unroll
            for (int i = 0; i < 4; i++)
#pragma unroll
                for (int j = 0; j < 4; j++) aa[i][j] = 0.0f;
#pragma unroll
            for (int kt = 0; kt < 2; kt++) {
                const int wA = mrow * PBE + kt * 8 + fth;
                unsigned ah[4], al[4];
                ah[0] = eqH[wA];          ah[1] = eqH[wA + 8 * PBE];
                ah[2] = eqH[wA + 4];      ah[3] = eqH[wA + 8 * PBE + 4];
                al[0] = eqL[wA];          al[1] = eqL[wA + 8 * PBE];
                al[2] = eqL[wA + 4];      al[3] = eqL[wA + 8 * PBE + 4];
#pragma unroll
                for (int nt = 0; nt < 4; nt++) {
                    const int wB = (jb + nt * 8 + fg) * PBE + kt * 8 + fth;
                    unsigned bh0 = wa1H[wB], bh1 = wa1H[wB + 4];
                    MMA16816(aa[nt], ah, bh0, bh1);
                    MMA16816(aa[nt], al, bh0, bh1);
                    unsigned bl0 = wa1L[wB], bl1 = wa1L[wB + 4];
                    MMA16816(aa[nt], ah, bl0, bl1);
                }
            }
            float p0 = 0.0f, p1 = 0.0f;
#pragma unroll
            for (int nt = 0; nt < 4; nt++) {
                const int j0 = jb + nt * 8 + 2 * fth;
                float w0 = sWa2[j0], w1 = sWa2[j0 + 1];
                float b0 = sba1[j0], b1 = sba1[j0 + 1];
                p0 = fmaf(fmaxf(aa[nt][0] + b0, 0.0f), w0, p0);
                p0 = fmaf(fmaxf(aa[nt][1] + b1, 0.0f), w1, p0);
                p1 = fmaf(fmaxf(aa[nt][2] + b0, 0.0f), w0, p1);
                p1 = fmaf(fmaxf(aa[nt][3] + b1, 0.0f), w1, p1);
            }
            // reduce over fth (quad)
            p0 += __shfl_xor_sync(0xffffffffu, p0, 1);
            p0 += __shfl_xor_sync(0xffffffffu, p0, 2);
            p1 += __shfl_xor_sync(0xffffffffu, p1, 1);
            p1 += __shfl_xor_sync(0xffffffffu, p1, 2);
            if (fth == 0) {
                float* dst = half ? sMWb : sMWa;
                dst[mrow]     = p0;
                dst[mrow + 8] = p1;
            }
        }
        // no sync needed here: stage 4 writes att fp32 (disjoint from eq/mask)

        // ---- stage 4 (mma): logits[64][256] = embq @ emboT ----
        {
            const int n0b = half * 128;
#pragma unroll
            for (int g = 0; g < 2; g++) {
                float lg[8][4];
#pragma unroll
                for (int i = 0; i < 8; i++)
#pragma unroll
                    for (int j = 0; j < 4; j++) lg[i][j] = 0.0f;
#pragma unroll
                for (int kt = 0; kt < 2; kt++) {
                    const int wA = mrow * PBE + kt * 8 + fth;
                    unsigned ah[4], al[4];
                    ah[0] = eqH[wA];          ah[1] = eqH[wA + 8 * PBE];
                    ah[2] = eqH[wA + 4];      ah[3] = eqH[wA + 8 * PBE + 4];
                    al[0] = eqL[wA];          al[1] = eqL[wA + 8 * PBE];
                    al[2] = eqL[wA + 4];      al[3] = eqL[wA + 8 * PBE + 4];
#pragma unroll
                    for (int nt = 0; nt < 8; nt++) {
                        const int wB = (n0b + g * 64 + nt * 8 + fg) * PBE + kt * 8 + fth;
                        unsigned bh0 = eoH[wB], bh1 = eoH[wB + 4];
                        MMA16816(lg[nt], ah, bh0, bh1);
                        MMA16816(lg[nt], al, bh0, bh1);
                        unsigned bl0 = eoL[wB], bl1 = eoL[wB + 4];
                        MMA16816(lg[nt], ah, bl0, bl1);
                    }
                }
#pragma unroll
                for (int nt = 0; nt < 8; nt++) {
                    const int k0 = n0b + g * 64 + nt * 8 + 2 * fth;
                    *(float2*)&sAtt[mrow * PATT + k0]       = make_float2(lg[nt][0], lg[nt][1]);
                    *(float2*)&sAtt[(mrow + 8) * PATT + k0] = make_float2(lg[nt][2], lg[nt][3]);
                }
            }
        }
        __syncthreads();                                        // (4)

        // ---- stage 5 (fused): softmax + mask/sum fold + bf16 conversion ----
        {
#pragma unroll
            for (int rr = 0; rr < 8; rr++) {
                const int r = wid * 8 + rr;
                const float* row = &sAtt[r * PATT + lane * 4];
                float4 a0 = *(const float4*)(row);
                float4 a1 = *(const float4*)(row + 128);
                float mx = fmaxf(fmaxf(fmaxf(a0.x, a0.y), fmaxf(a0.z, a0.w)),
                                 fmaxf(fmaxf(a1.x, a1.y), fmaxf(a1.z, a1.w)));
#pragma unroll
                for (int o = 16; o > 0; o >>= 1) mx = fmaxf(mx, __shfl_xor_sync(0xffffffffu, mx, o));
                float e0 = __expf(a0.x - mx), e1 = __expf(a0.y - mx);
                float e2 = __expf(a0.z - mx), e3 = __expf(a0.w - mx);
                float e4 = __expf(a1.x - mx), e5 = __expf(a1.y - mx);
                float e6 = __expf(a1.z - mx), e7 = __expf(a1.w - mx);
                float s = ((e0 + e1) + (e2 + e3)) + ((e4 + e5) + (e6 + e7));
#pragma unroll
                for (int o = 16; o > 0; o >>= 1) s += __shfl_xor_sync(0xffffffffu, s, o);
                float ml = sMWa[r] + sMWb[r] + ba2v;
                float wr = __fdividef(1.0f, (1.0f + __expf(-ml)) * s);  // sigmoid(ml)/s
                unsigned h0, l0, h1, l1;
                const int w0 = r * PAF + lane * 2;
                split2(e0 * wr, e1 * wr, h0, l0);
                split2(e2 * wr, e3 * wr, h1, l1);
                *(uint2*)&ahiF[w0] = make_uint2(h0, h1);
                *(uint2*)&aloF[w0] = make_uint2(l0, l1);
                split2(e4 * wr, e5 * wr, h0, l0);
                split2(e6 * wr, e7 * wr, h1, l1);
                *(uint2*)&ahiF[w0 + 64] = make_uint2(h0, h1);
                *(uint2*)&aloF[w0 + 64] = make_uint2(l0, l1);
            }
        }
        __syncthreads();                                        // (5)

        // ---- stage 6 (mma): acc += att @ V^T, 2 phases of 128 k, cp.async V ----
#pragma unroll
        for (int ph = 0; ph < 2; ph++) {
            // async-copy precomputed V bf16 half into smem
#pragma unroll
            for (int it = 0; it < 16; it++) {
                int id = t + it * 256;          // 0..4095
                int c = id >> 5, s = id & 31;
                const unsigned* gsrc;
                unsigned sdst;
                if (s < 16) {
                    gsrc = g_vhi + vbase + c * 128 + ph * 64 + s * 4;
                    sdst = sb_u32 + (unsigned)(OFF_ATT + c * PV + s * 4) * 4u;
                } else {
                    int s2 = s - 16;
                    gsrc = g_vlo + vbase + c * 128 + ph * 64 + s2 * 4;
                    sdst = sb_u32 + (unsigned)(OFF_ATT + 8704 + c * PV + s2 * 4) * 4u;
                }
                asm volatile("cp.async.cg.shared.global [%0], [%1], 16;"
                             :: "r"(sdst), "l"(gsrc) : "memory");
            }
            asm volatile("cp.async.commit_group;" ::: "memory");
            asm volatile("cp.async.wait_group 0;" ::: "memory");
            __syncthreads();                                    // (6/8)

#pragma unroll
            for (int kt = 0; kt < 8; kt++) {
                const int wA = mrow * PAF + ph * 64 + kt * 8 + fth;
                unsigned ah[4], al[4];
                ah[0] = ahiF[wA];            ah[1] = ahiF[wA + 8 * PAF];
                ah[2] = ahiF[wA + 4];        ah[3] = ahiF[wA + 8 * PAF + 4];
                al[0] = aloF[wA];            al[1] = aloF[wA + 8 * PAF];
                al[2] = aloF[wA + 4];        al[3] = aloF[wA + 8 * PAF + 4];
                unsigned bh[8][2];
#pragma unroll
                for (int nt = 0; nt < 8; nt++) {
                    const int wB = (cb + nt * 8 + fg) * PV + kt * 8 + fth;
                    bh[nt][0] = vhiW[wB];
                    bh[nt][1] = vhiW[wB + 4];
                    MMA16816(acc[nt], ah, bh[nt][0], bh[nt][1]);
                }
#pragma unroll
                for (int nt = 0; nt < 8; nt++)
                    MMA16816(acc[nt], al, bh[nt][0], bh[nt][1]);
#pragma unroll
                for (int nt = 0; nt < 8; nt++) {
                    const int wB = (cb + nt * 8 + fg) * PV + kt * 8 + fth;
                    unsigned b0 = vloW[wB], b1 = vloW[wB + 4];
                    MMA16816(acc[nt], ah, b0, b1);
                }
            }
            __syncthreads();                                    // (7/9)
        }
    } // n loop

    // ---- epilogue: sigmoid, stage transposed via smem, coalesced store ----
#pragma unroll
    for (int nt = 0; nt < 8; nt++) {
        int c0 = cb + nt * 8 + 2 * fth;
        sOut[c0 * POUT + mrow]           = 1.0f / (1.0f + __expf(-acc[nt][0]));
        sOut[(c0 + 1) * POUT + mrow]     = 1.0f / (1.0f + __expf(-acc[nt][1]));
        sOut[c0 * POUT + mrow + 8]       = 1.0f / (1.0f + __expf(-acc[nt][2]));
        sOut[(c0 + 1) * POUT + mrow + 8] = 1.0f / (1.0f + __expf(-acc[nt][3]));
    }
    __syncthreads();

    float* outp = dout + (size_t)b * CELLD * QQ + qt * TQ;
    for (int id = t; id < CELLD * TQ; id += NTHR) {
        int c = id >> 6, r = id & 63;
        outp[(size_t)c * QQ + r] = sOut[c * POUT + r];
    }
}

// =================== launch ===================
extern "C" void kernel_launch(void* const* d_in, const int* in_sizes, int n_in,
                              void* d_out, int out_size)
{
    (void)in_sizes; (void)n_in; (void)out_size;
    const float* view_cell = (const float*)d_in[0];
    const float* pose_o    = (const float*)d_in[1];
    const float* pose_q    = (const float*)d_in[2];
    const float* Wk1 = (const float*)d_in[3];
    const float* bk1 = (const float*)d_in[4];
    const float* Wk2 = (const float*)d_in[5];
    const float* bk2 = (const float*)d_in[6];
    const float* Wq1 = (const float*)d_in[7];
    const float* bq1 = (const float*)d_in[8];
    const float* Wq2 = (const float*)d_in[9];
    const float* bq2 = (const float*)d_in[10];
    const float* Wa1 = (const float*)d_in[11];
    const float* ba1 = (const float*)d_in[12];
    const float* Wa2 = (const float*)d_in[13];
    const float* ba2 = (const float*)d_in[14];

    float* out = (float*)d_out;
    float* out_poq = out + (size_t)BB * CELLD * QQ;           // [32,8,7]
    float* out_pqq = out_poq + (size_t)BB * NN * 7;           // [32,1,7]

    cudaFuncSetAttribute(kB, cudaFuncAttributeMaxDynamicSharedMemorySize, SMEM_BYTES);

    kA<<<1, 256>>>(pose_o, pose_q, Wk1, bk1, Wk2, bk2, out_poq, out_pqq);
    kA2<<<BND, 256>>>(view_cell);
    kB<<<dim3(QQ / TQ, BB), NTHR, SMEM_BYTES>>>(Wq1, bq1, Wq2, bq2,
                                                Wa1, ba1, Wa2, ba2, out);
}

// round 16
// speedup vs baseline: 1.1085x; 1.1085x over previous
#include <cuda_runtime.h>
#include <cuda_bf16.h>
#include <math.h>

// Problem constants
#define HH    16
#define WW    16
#define DD    6
#define EMBD  32
#define CELLD 128
#define BB    32
#define NN    8
#define BND   256           // B*N
#define QQ    1536          // D*H*W
#define KKEY  256           // H*W
#define TQ    64            // q rows per block
#define NTHR  256

typedef unsigned long long u64;

// packed dual-FMA (FFMA2)
#define FMA2(d, a, b, c) \
    asm("fma.rn.f32x2 %0, %1, %2, %3;" : "=l"(d) : "l"(a), "l"(b), "l"(c))

__device__ __forceinline__ float u2lo(u64 u) { return __uint_as_float((unsigned)(u & 0xffffffffu)); }
__device__ __forceinline__ float u2hi(u64 u) { return __uint_as_float((unsigned)(u >> 32)); }
__device__ __forceinline__ float u2sum(u64 u) { return u2lo(u) + u2hi(u); }

struct F4U { union { float4 f; u64 u[2]; }; };

// warp mma: D(f32 4regs) += A(bf16 4regs) * B(bf16 2regs), m16n8k16
#define MMA16816(d, a, b0, b1) \
    asm volatile("mma.sync.aligned.m16n8k16.row.col.f32.bf16.bf16.f32 " \
        "{%0,%1,%2,%3}, {%4,%5,%6,%7}, {%8,%9}, {%0,%1,%2,%3};" \
        : "+f"((d)[0]), "+f"((d)[1]), "+f"((d)[2]), "+f"((d)[3]) \
        : "r"((a)[0]), "r"((a)[1]), "r"((a)[2]), "r"((a)[3]), "r"(b0), "r"(b1))

__device__ __forceinline__ unsigned pack_bf16x2(float f0, float f1) {
    unsigned r;
    asm("cvt.rn.bf16x2.f32 %0, %1, %2;" : "=r"(r) : "f"(f1), "f"(f0));
    return r;
}

__device__ __forceinline__ void split2(float f0, float f1, unsigned& uh, unsigned& ul) {
    uh = pack_bf16x2(f0, f1);
    float h0 = __uint_as_float(uh << 16);
    float h1 = __uint_as_float(uh & 0xffff0000u);
    ul = pack_bf16x2(f0 - h0, f1 - h1);
}

// ---- scratch (device globals; no allocations allowed) ----
__device__ float g_pose_trans[BND * 12];
__device__ __align__(16) float g_embo[KKEY * EMBD];

__device__ __forceinline__ float lin16(int i) { return -1.0f + (2.0f / 15.0f) * (float)i; }

__device__ __forceinline__ void mat2quat7(const float* m, float* out7) {
    float m00 = m[0], m01 = m[1], m02 = m[2], tx = m[3];
    float m10 = m[4], m11 = m[5], m12 = m[6], ty = m[7];
    float m20 = m[8], m21 = m[9], m22 = m[10], tz = m[11];
    float t, q0, q1, q2, q3;
    if (m22 < 0.0f) {
        if (m00 > m11) {
            t = 1.0f + m00 - m11 - m22;
            q0 = t; q1 = m01 + m10; q2 = m20 + m02; q3 = m12 - m21;
        } else {
            t = 1.0f - m00 + m11 - m22;
            q0 = m01 + m10; q1 = t; q2 = m12 + m21; q3 = m20 - m02;
        }
    } else {
        if (m00 < -m11) {
            t = 1.0f - m00 - m11 + m22;
            q0 = m20 + m02; q1 = m12 + m21; q2 = t; q3 = m01 - m10;
        } else {
            t = 1.0f + m00 + m11 + m22;
            q0 = m12 - m21; q1 = m20 - m02; q2 = m01 - m10; q3 = t;
        }
    }
    float s = 0.5f / sqrtf(t);
    out7[0] = tx; out7[1] = ty; out7[2] = tz;
    out7[3] = q0 * s; out7[4] = q1 * s; out7[5] = q2 * s; out7[6] = q3 * s;
}

// =================== Kernel A: poses (1 block) ===================
__global__ void kA(const float* __restrict__ pose_o, const float* __restrict__ pose_q,
                   float* __restrict__ out_poq, float* __restrict__ out_pqq)
{
    int t = threadIdx.x;  // 256 threads, 1 block

    {
        float q7[7];
        mat2quat7(pose_o + t * 12, q7);
#pragma unroll
        for (int i = 0; i < 7; i++) out_poq[t * 7 + i] = q7[i];
    }
    if (t < BB) {
        float q7[7];
        mat2quat7(pose_q + t * 12, q7);
#pragma unroll
        for (int i = 0; i < 7; i++) out_pqq[t * 7 + i] = q7[i];
    }

    // relative pose: inv([Ro|to]) @ [Rq|tq]  (fp64 adjugate inverse)
    {
        const float* po = pose_o + t * 12;
        const float* pq = pose_q + (t >> 3) * 12;
        double a[3][3], to[3], Rq[3][3], tq[3];
#pragma unroll
        for (int i = 0; i < 3; i++) {
#pragma unroll
            for (int j = 0; j < 3; j++) { a[i][j] = po[i * 4 + j]; Rq[i][j] = pq[i * 4 + j]; }
            to[i] = po[i * 4 + 3]; tq[i] = pq[i * 4 + 3];
        }
        double c00 = a[1][1] * a[2][2] - a[1][2] * a[2][1];
        double c01 = a[1][2] * a[2][0] - a[1][0] * a[2][2];
        double c02 = a[1][0] * a[2][1] - a[1][1] * a[2][0];
        double det = a[0][0] * c00 + a[0][1] * c01 + a[0][2] * c02;
        double inv[3][3];
        inv[0][0] = c00 / det;
        inv[1][0] = c01 / det;
        inv[2][0] = c02 / det;
        inv[0][1] = (a[0][2] * a[2][1] - a[0][1] * a[2][2]) / det;
        inv[1][1] = (a[0][0] * a[2][2] - a[0][2] * a[2][0]) / det;
        inv[2][1] = (a[0][1] * a[2][0] - a[0][0] * a[2][1]) / det;
        inv[0][2] = (a[0][1] * a[1][2] - a[0][2] * a[1][1]) / det;
        inv[1][2] = (a[0][2] * a[1][0] - a[0][0] * a[1][2]) / det;
        inv[2][2] = (a[0][0] * a[1][1] - a[0][1] * a[1][0]) / det;
#pragma unroll
        for (int i = 0; i < 3; i++) {
#pragma unroll
            for (int j = 0; j < 3; j++) {
                double s = 0.0;
#pragma unroll
                for (int k = 0; k < 3; k++) s += inv[i][k] * Rq[k][j];
                g_pose_trans[t * 12 + i * 4 + j] = (float)s;
            }
            double s = 0.0;
#pragma unroll
            for (int k = 0; k < 3; k++) s += inv[i][k] * (tq[k] - to[k]);
            g_pose_trans[t * 12 + i * 4 + 3] = (float)s;
        }
    }
}

// =================== Kernel Ae: key embeddings (32 blocks) ===================
// one (key, e) pair per thread: embO[key][e] = relu(code@Wk1+b) . Wk2[:,e] + b
__global__ void kAe(const float* __restrict__ Wk1, const float* __restrict__ bk1,
                    const float* __restrict__ Wk2, const float* __restrict__ bk2)
{
    const int t   = threadIdx.x;              // 0..255
    const int key = blockIdx.x * 8 + (t >> 5);
    const int e   = t & 31;
    const float c0 = lin16(key >> 4), c1 = lin16(key & 15);
    float s = bk2[e];
#pragma unroll 8
    for (int j = 0; j < 128; j++) {
        float h = fmaf(c0, Wk1[j], fmaf(c1, Wk1[128 + j], bk1[j]));
        h = fmaxf(h, 0.0f);
        s = fmaf(h, Wk2[j * EMBD + e], s);
    }
    g_embo[key * EMBD + e] = s;
}

// =================== Kernel B: fused main (256 thr, TQ=64, mma, low-sync) ===================
#define PATT  260   // att [64][260] fp32
#define POUT  66    // epilogue staging [128][66] (att-region union)
#define PV    68    // V half bf16 pitch (words, 128 k values = 64 data words)
#define PBH   132   // hid bf16 pitch (words)
#define PAF   132   // full-row att bf16 pitch (words)
#define PBE   20    // e-dim bf16 fragment pitch (words)

#define OFF_WQ2H  0                           // 4224
#define OFF_WQ2L  4224                        // 4224
#define OFF_EOH   8448                        // 5120
#define OFF_EOL   13568                       // 5120
#define OFF_WA1H  18688                       // 1280
#define OFF_WA1L  19968                       // 1280
#define OFF_ATT   21248                       // 17408: unions att fp32 / out / V-half bf16
#define OFF_TILE  38656                       // 16896: unions hid+eq / att bf16 full-row
#define OFF_BQ2   55552                       // 32
#define OFF_WA2   55584                       // 64
#define OFF_BA1   55648                       // 64
#define OFF_MASKA 55712                       // 64 (half-0 mask partials)
#define OFF_MASKB 55776                       // 64 (half-1 mask partials)
#define OFF_POSE  55840                       // 96
#define OFF_CODE  55936                       // 192
#define SMEM_FLOATS 56128
#define SMEM_BYTES  (SMEM_FLOATS * 4)

extern __shared__ float sm[];

__global__ void __launch_bounds__(NTHR, 1)
kB(const float* __restrict__ vc,
   const float* __restrict__ Wq1, const float* __restrict__ bq1,
   const float* __restrict__ Wq2, const float* __restrict__ bq2,
   const float* __restrict__ Wa1, const float* __restrict__ ba1,
   const float* __restrict__ Wa2, const float* __restrict__ ba2,
   float* __restrict__ dout)
{
    const int t  = threadIdx.x;          // 0..255
    const int qt = blockIdx.x;           // 0..23
    const int b  = blockIdx.y;           // 0..31

    float* sAtt  = sm + OFF_ATT;   // fp32 logits (stage 4 -> softmax)
    float* sOut  = sm + OFF_ATT;   // union (epilogue)
    float* sbq2  = sm + OFF_BQ2;
    float* sWa2  = sm + OFF_WA2;
    float* sba1  = sm + OFF_BA1;
    float* sMWa  = sm + OFF_MASKA;
    float* sMWb  = sm + OFF_MASKB;
    float* sPose = sm + OFF_POSE;
    float* sCode = sm + OFF_CODE;
    unsigned* wq2H = (unsigned*)(sm + OFF_WQ2H);  // [32 e][132] words
    unsigned* wq2L = (unsigned*)(sm + OFF_WQ2L);
    unsigned* eoH  = (unsigned*)(sm + OFF_EOH);   // [256 k][20] words
    unsigned* eoL  = (unsigned*)(sm + OFF_EOL);
    unsigned* wa1H = (unsigned*)(sm + OFF_WA1H);  // [64 j][20] words
    unsigned* wa1L = (unsigned*)(sm + OFF_WA1L);
    unsigned* hidH = (unsigned*)(sm + OFF_TILE);            // [64 q][132]
    unsigned* hidL = (unsigned*)(sm + OFF_TILE + 8448);
    unsigned* eqH  = (unsigned*)(sm + OFF_TILE + 13824);    // [64 q][20]
    unsigned* eqL  = (unsigned*)(sm + OFF_TILE + 15104);
    unsigned* ahiF = (unsigned*)(sm + OFF_TILE);            // [64 q][132] full-row att bf16
    unsigned* aloF = (unsigned*)(sm + OFF_TILE + 8448);
    unsigned* vhiW = (unsigned*)(sm + OFF_ATT);             // [128 c][68] V half bf16
    unsigned* vloW = (unsigned*)(sm + OFF_ATT + 8704);

    // ---- one-time loads / conversions ----
    // Wq2 [256 h][32 e] -> split-bf16 K-major tiles [32 e][128 hpair words]
    {
        const int e = t >> 3;
        const int hp0 = (t & 7) * 16;
#pragma unroll
        for (int i = 0; i < 16; i++) {
            int hp = hp0 + i;
            float f0 = Wq2[(2 * hp) * 32 + e];
            float f1 = Wq2[(2 * hp + 1) * 32 + e];
            unsigned uh, ul;
            split2(f0, f1, uh, ul);
            wq2H[e * PBH + hp] = uh;
            wq2L[e * PBH + hp] = ul;
        }
    }
    // embO [256 k][32 e] fp32 -> split-bf16 [k][16 ewords]
    {
        const float* ep = g_embo + t * 32;
#pragma unroll
        for (int w = 0; w < 16; w++) {
            unsigned uh, ul;
            split2(ep[2 * w], ep[2 * w + 1], uh, ul);
            eoH[t * PBE + w] = uh;
            eoL[t * PBE + w] = ul;
        }
    }
    // Wa1 [32 e][64 j] -> split-bf16 transposed [j][16 ewords]
    if (t < 64) {
#pragma unroll
        for (int w = 0; w < 16; w++) {
            float f0 = Wa1[(2 * w) * 64 + t];
            float f1 = Wa1[(2 * w + 1) * 64 + t];
            unsigned uh, ul;
            split2(f0, f1, uh, ul);
            wa1H[t * PBE + w] = uh;
            wa1L[t * PBE + w] = ul;
        }
    }
    if (t < 64) { sWa2[t] = Wa2[t]; sba1[t] = ba1[t]; }
    if (t < 32) sbq2[t] = bq2[t];
    if (t < 96) sPose[t] = g_pose_trans[b * 96 + t];
    if (t < TQ) {
        int q = qt * TQ + t;
        int d = q >> 8, rm = q & 255;
        sCode[t * 3 + 0] = 0.2f * (float)d;
        sCode[t * 3 + 1] = lin16(rm >> 4);
        sCode[t * 3 + 2] = lin16(rm & 15);
    }

    // stage-1 per-thread weights: two adjacent Wq1 columns (h = 2hp, 2hp+1)
    const int hp   = t & 127;
    const int r0s1 = (t >> 7) * 32;      // rows [r0s1, r0s1+32)
    float wqa[15], wqb[15];
#pragma unroll
    for (int i = 0; i < 15; i++) {
        wqa[i] = Wq1[i * 256 + 2 * hp];
        wqb[i] = Wq1[i * 256 + 2 * hp + 1];
    }
    const float wba = bq1[2 * hp], wbb = bq1[2 * hp + 1];
    const float ba2v = ba2[0];

    // mma tiling: 8 warps = 4 m-tiles x 2 halves
    const int wid = t >> 5, lane = t & 31;
    const int fg  = lane >> 2, fth = lane & 3;       // fragment coords
    const int mrow = (wid >> 1) * 16 + fg;           // q row base
    const int half = wid & 1;
    const int cb   = half * 64;                      // stage-6 c half
    const int nb2  = half * 16;                      // stage-2 e half

    float acc[8][4];
#pragma unroll
    for (int i = 0; i < 8; i++)
#pragma unroll
        for (int j = 0; j < 4; j++) acc[i][j] = 0.0f;

    __syncthreads();

    for (int n = 0; n < NN; n++) {
        const int bn = b * NN + n;
        const float* vcn = vc + (size_t)bn * CELLD * KKEY;

        // ---- stage 1: hidden = relu(inp @ Wq1 + b), written as split-bf16 ----
        {
            const float* ps = &sPose[n * 12];
            float basea = wba, baseb = wbb;
#pragma unroll
            for (int i = 0; i < 12; i++) {
                basea = fmaf(ps[i], wqa[i], basea);
                baseb = fmaf(ps[i], wqb[i], baseb);
            }
#pragma unroll 4
            for (int rr = 0; rr < 32; rr++) {
                const int r = r0s1 + rr;
                float c0 = sCode[r * 3 + 0], c1 = sCode[r * 3 + 1], c2 = sCode[r * 3 + 2];
                float va = basea, vb = baseb;
                va = fmaf(c0, wqa[12], va); vb = fmaf(c0, wqb[12], vb);
                va = fmaf(c1, wqa[13], va); vb = fmaf(c1, wqb[13], vb);
                va = fmaf(c2, wqa[14], va); vb = fmaf(c2, wqb[14], vb);
                va = fmaxf(va, 0.0f); vb = fmaxf(vb, 0.0f);
                unsigned uh, ul;
                split2(va, vb, uh, ul);
                hidH[r * PBH + hp] = uh;
                hidL[r * PBH + hp] = ul;
            }
        }
        __syncthreads();                                        // (1)

        // ---- stage 2 (mma): embq = hid @ Wq2 + b -> split-bf16 fragments ----
        {
            float ea[2][4];
#pragma unroll
            for (int i = 0; i < 2; i++)
#pragma unroll
                for (int j = 0; j < 4; j++) ea[i][j] = 0.0f;
#pragma unroll
            for (int ks = 0; ks < 16; ks++) {
                const int wA = mrow * PBH + ks * 8 + fth;
                unsigned ah[4], al[4];
                ah[0] = hidH[wA];          ah[1] = hidH[wA + 8 * PBH];
                ah[2] = hidH[wA + 4];      ah[3] = hidH[wA + 8 * PBH + 4];
                al[0] = hidL[wA];          al[1] = hidL[wA + 8 * PBH];
                al[2] = hidL[wA + 4];      al[3] = hidL[wA + 8 * PBH + 4];
#pragma unroll
                for (int nt = 0; nt < 2; nt++) {
                    const int wB = (nb2 + nt * 8 + fg) * PBH + ks * 8 + fth;
                    unsigned bh0 = wq2H[wB], bh1 = wq2H[wB + 4];
                    MMA16816(ea[nt], ah, bh0, bh1);
                    MMA16816(ea[nt], al, bh0, bh1);
                    unsigned bl0 = wq2L[wB], bl1 = wq2L[wB + 4];
                    MMA16816(ea[nt], ah, bl0, bl1);
                }
            }
            __syncthreads();                                    // (2) hid reads done
#pragma unroll
            for (int nt = 0; nt < 2; nt++) {
                const int e0 = nb2 + nt * 8 + 2 * fth;
                unsigned uh, ul;
                split2(ea[nt][0] + sbq2[e0], ea[nt][1] + sbq2[e0 + 1], uh, ul);
                eqH[mrow * PBE + (e0 >> 1)] = uh;
                eqL[mrow * PBE + (e0 >> 1)] = ul;
                split2(ea[nt][2] + sbq2[e0], ea[nt][3] + sbq2[e0 + 1], uh, ul);
                eqH[(mrow + 8) * PBE + (e0 >> 1)] = uh;
                eqL[(mrow + 8) * PBE + (e0 >> 1)] = ul;
            }
        }
        __syncthreads();                                        // (3)

        // ---- stage 3 (mma, in-register): mask partials = relu(embq@Wa1+ba1)@Wa2 ----
        {
            const int jb = half * 32;
            float aa[4][4];
#pragma unroll
            for (int i = 0; i < 4; i++)
#pragma unroll
                for (int j = 0; j < 4; j++) aa[i][j] = 0.0f;
#pragma unroll
            for (int kt = 0; kt < 2; kt++) {
                const int wA = mrow * PBE + kt * 8 + fth;
                unsigned ah[4], al[4];
                ah[0] = eqH[wA];          ah[1] = eqH[wA + 8 * PBE];
                ah[2] = eqH[wA + 4];      ah[3] = eqH[wA + 8 * PBE + 4];
                al[0] = eqL[wA];          al[1] = eqL[wA + 8 * PBE];
                al[2] = eqL[wA + 4];      al[3] = eqL[wA + 8 * PBE + 4];
#pragma unroll
                for (int nt = 0; nt < 4; nt++) {
                    const int wB = (jb + nt * 8 + fg) * PBE + kt * 8 + fth;
                    unsigned bh0 = wa1H[wB], bh1 = wa1H[wB + 4];
                    MMA16816(aa[nt], ah, bh0, bh1);
                    MMA16816(aa[nt], al, bh0, bh1);
                    unsigned bl0 = wa1L[wB], bl1 = wa1L[wB + 4];
                    MMA16816(aa[nt], ah, bl0, bl1);
                }
            }
            float p0 = 0.0f, p1 = 0.0f;
#pragma unroll
            for (int nt = 0; nt < 4; nt++) {
                const int j0 = jb + nt * 8 + 2 * fth;
                float w0 = sWa2[j0], w1 = sWa2[j0 + 1];
                float b0 = sba1[j0], b1 = sba1[j0 + 1];
                p0 = fmaf(fmaxf(aa[nt][0] + b0, 0.0f), w0, p0);
                p0 = fmaf(fmaxf(aa[nt][1] + b1, 0.0f), w1, p0);
                p1 = fmaf(fmaxf(aa[nt][2] + b0, 0.0f), w0, p1);
                p1 = fmaf(fmaxf(aa[nt][3] + b1, 0.0f), w1, p1);
            }
            // reduce over fth (quad)
            p0 += __shfl_xor_sync(0xffffffffu, p0, 1);
            p0 += __shfl_xor_sync(0xffffffffu, p0, 2);
            p1 += __shfl_xor_sync(0xffffffffu, p1, 1);
            p1 += __shfl_xor_sync(0xffffffffu, p1, 2);
            if (fth == 0) {
                float* dst = half ? sMWb : sMWa;
                dst[mrow]     = p0;
                dst[mrow + 8] = p1;
            }
        }
        // no sync needed here: stage 4 writes att fp32 (disjoint from eq/mask)

        // ---- stage 4 (mma): logits[64][256] = embq @ emboT ----
        {
            const int n0b = half * 128;
#pragma unroll
            for (int g = 0; g < 2; g++) {
                float lg[8][4];
#pragma unroll
                for (int i = 0; i < 8; i++)
#pragma unroll
                    for (int j = 0; j < 4; j++) lg[i][j] = 0.0f;
#pragma unroll
                for (int kt = 0; kt < 2; kt++) {
                    const int wA = mrow * PBE + kt * 8 + fth;
                    unsigned ah[4], al[4];
                    ah[0] = eqH[wA];          ah[1] = eqH[wA + 8 * PBE];
                    ah[2] = eqH[wA + 4];      ah[3] = eqH[wA + 8 * PBE + 4];
                    al[0] = eqL[wA];          al[1] = eqL[wA + 8 * PBE];
                    al[2] = eqL[wA + 4];      al[3] = eqL[wA + 8 * PBE + 4];
#pragma unroll
                    for (int nt = 0; nt < 8; nt++) {
                        const int wB = (n0b + g * 64 + nt * 8 + fg) * PBE + kt * 8 + fth;
                        unsigned bh0 = eoH[wB], bh1 = eoH[wB + 4];
                        MMA16816(lg[nt], ah, bh0, bh1);
                        MMA16816(lg[nt], al, bh0, bh1);
                        unsigned bl0 = eoL[wB], bl1 = eoL[wB + 4];
                        MMA16816(lg[nt], ah, bl0, bl1);
                    }
                }
#pragma unroll
                for (int nt = 0; nt < 8; nt++) {
                    const int k0 = n0b + g * 64 + nt * 8 + 2 * fth;
                    *(float2*)&sAtt[mrow * PATT + k0]       = make_float2(lg[nt][0], lg[nt][1]);
                    *(float2*)&sAtt[(mrow + 8) * PATT + k0] = make_float2(lg[nt][2], lg[nt][3]);
                }
            }
        }
        __syncthreads();                                        // (4)

        // ---- stage 5 (fused): softmax + mask/sum fold + bf16 conversion ----
        {
#pragma unroll
            for (int rr = 0; rr < 8; rr++) {
                const int r = wid * 8 + rr;
                const float* row = &sAtt[r * PATT + lane * 4];
                float4 a0 = *(const float4*)(row);
                float4 a1 = *(const float4*)(row + 128);
                float mx = fmaxf(fmaxf(fmaxf(a0.x, a0.y), fmaxf(a0.z, a0.w)),
                                 fmaxf(fmaxf(a1.x, a1.y), fmaxf(a1.z, a1.w)));
#pragma unroll
                for (int o = 16; o > 0; o >>= 1) mx = fmaxf(mx, __shfl_xor_sync(0xffffffffu, mx, o));
                float e0 = __expf(a0.x - mx), e1 = __expf(a0.y - mx);
                float e2 = __expf(a0.z - mx), e3 = __expf(a0.w - mx);
                float e4 = __expf(a1.x - mx), e5 = __expf(a1.y - mx);
                float e6 = __expf(a1.z - mx), e7 = __expf(a1.w - mx);
                float s = ((e0 + e1) + (e2 + e3)) + ((e4 + e5) + (e6 + e7));
#pragma unroll
                for (int o = 16; o > 0; o >>= 1) s += __shfl_xor_sync(0xffffffffu, s, o);
                float ml = sMWa[r] + sMWb[r] + ba2v;
                float wr = __fdividef(1.0f, (1.0f + __expf(-ml)) * s);  // sigmoid(ml)/s
                unsigned h0, l0, h1, l1;
                const int w0 = r * PAF + lane * 2;
                split2(e0 * wr, e1 * wr, h0, l0);
                split2(e2 * wr, e3 * wr, h1, l1);
                *(uint2*)&ahiF[w0] = make_uint2(h0, h1);
                *(uint2*)&aloF[w0] = make_uint2(l0, l1);
                split2(e4 * wr, e5 * wr, h0, l0);
                split2(e6 * wr, e7 * wr, h1, l1);
                *(uint2*)&ahiF[w0 + 64] = make_uint2(h0, h1);
                *(uint2*)&aloF[w0 + 64] = make_uint2(l0, l1);
            }
        }
        __syncthreads();                                        // (5)

        // ---- stage 6 (mma): acc += att @ V^T, 2 phases of 128 k each ----
#pragma unroll
        for (int ph = 0; ph < 2; ph++) {
            // convert V k-half [128 c][128 k] -> bf16 hi/lo (clobbers att fp32: dead)
#pragma unroll
            for (int it = 0; it < 16; it++) {
                int id = t + it * 256;
                int c = id >> 5, f = id & 31;
                float4 vv = *(const float4*)(vcn + c * 256 + ph * 128 + f * 4);
                unsigned h0, l0, h1, l1;
                split2(vv.x, vv.y, h0, l0);
                split2(vv.z, vv.w, h1, l1);
                *(uint2*)&vhiW[c * PV + f * 2] = make_uint2(h0, h1);
                *(uint2*)&vloW[c * PV + f * 2] = make_uint2(l0, l1);
            }
            __syncthreads();                                    // (6/8)

#pragma unroll
            for (int kt = 0; kt < 8; kt++) {
                const int wA = mrow * PAF + ph * 64 + kt * 8 + fth;
                unsigned ah[4], al[4];
                ah[0] = ahiF[wA];            ah[1] = ahiF[wA + 8 * PAF];
                ah[2] = ahiF[wA + 4];        ah[3] = ahiF[wA + 8 * PAF + 4];
                al[0] = aloF[wA];            al[1] = aloF[wA + 8 * PAF];
                al[2] = aloF[wA + 4];        al[3] = aloF[wA + 8 * PAF + 4];
                unsigned bh[8][2];
#pragma unroll
                for (int nt = 0; nt < 8; nt++) {
                    const int wB = (cb + nt * 8 + fg) * PV + kt * 8 + fth;
                    bh[nt][0] = vhiW[wB];
                    bh[nt][1] = vhiW[wB + 4];
                    MMA16816(acc[nt], ah, bh[nt][0], bh[nt][1]);
                }
#pragma unroll
                for (int nt = 0; nt < 8; nt++)
                    MMA16816(acc[nt], al, bh[nt][0], bh[nt][1]);
#pragma unroll
                for (int nt = 0; nt < 8; nt++) {
                    const int wB = (cb + nt * 8 + fg) * PV + kt * 8 + fth;
                    unsigned b0 = vloW[wB], b1 = vloW[wB + 4];
                    MMA16816(acc[nt], ah, b0, b1);
                }
            }
            __syncthreads();                                    // (7/9)
        }
    } // n loop

    // ---- epilogue: sigmoid, stage transposed via smem, coalesced store ----
#pragma unroll
    for (int nt = 0; nt < 8; nt++) {
        int c0 = cb + nt * 8 + 2 * fth;
        sOut[c0 * POUT + mrow]           = 1.0f / (1.0f + __expf(-acc[nt][0]));
        sOut[(c0 + 1) * POUT + mrow]     = 1.0f / (1.0f + __expf(-acc[nt][1]));
        sOut[c0 * POUT + mrow + 8]       = 1.0f / (1.0f + __expf(-acc[nt][2]));
        sOut[(c0 + 1) * POUT + mrow + 8] = 1.0f / (1.0f + __expf(-acc[nt][3]));
    }
    __syncthreads();

    float* outp = dout + (size_t)b * CELLD * QQ + qt * TQ;
    for (int id = t; id < CELLD * TQ; id += NTHR) {
        int c = id >> 6, r = id & 63;
        outp[(size_t)c * QQ + r] = sOut[c * POUT + r];
    }
}

// =================== launch ===================
extern "C" void kernel_launch(void* const* d_in, const int* in_sizes, int n_in,
                              void* d_out, int out_size)
{
    (void)in_sizes; (void)n_in; (void)out_size;
    const float* view_cell = (const float*)d_in[0];
    const float* pose_o    = (const float*)d_in[1];
    const float* pose_q    = (const float*)d_in[2];
    const float* Wk1 = (const float*)d_in[3];
    const float* bk1 = (const float*)d_in[4];
    const float* Wk2 = (const float*)d_in[5];
    const float* bk2 = (const float*)d_in[6];
    const float* Wq1 = (const float*)d_in[7];
    const float* bq1 = (const float*)d_in[8];
    const float* Wq2 = (const float*)d_in[9];
    const float* bq2 = (const float*)d_in[10];
    const float* Wa1 = (const float*)d_in[11];
    const float* ba1 = (const float*)d_in[12];
    const float* Wa2 = (const float*)d_in[13];
    const float* ba2 = (const float*)d_in[14];

    float* out = (float*)d_out;
    float* out_poq = out + (size_t)BB * CELLD * QQ;           // [32,8,7]
    float* out_pqq = out_poq + (size_t)BB * NN * 7;           // [32,1,7]

    cudaFuncSetAttribute(kB, cudaFuncAttributeMaxDynamicSharedMemorySize, SMEM_BYTES);

    kA<<<1, 256>>>(pose_o, pose_q, out_poq, out_pqq);
    kAe<<<32, 256>>>(Wk1, bk1, Wk2, bk2);
    kB<<<dim3(QQ / TQ, BB), NTHR, SMEM_BYTES>>>(view_cell, Wq1, bq1, Wq2, bq2,
                                                Wa1, ba1, Wa2, ba2, out);
}

// round 17
// speedup vs baseline: 1.1355x; 1.0243x over previous
#include <cuda_runtime.h>
#include <cuda_bf16.h>
#include <math.h>

// Problem constants
#define HH    16
#define WW    16
#define DD    6
#define EMBD  32
#define CELLD 128
#define BB    32
#define NN    8
#define BND   256           // B*N
#define QQ    1536          // D*H*W
#define KKEY  256           // H*W
#define TQ    64            // q rows per block
#define NTHR  256

typedef unsigned long long u64;

// packed dual-FMA (FFMA2)
#define FMA2(d, a, b, c) \
    asm("fma.rn.f32x2 %0, %1, %2, %3;" : "=l"(d) : "l"(a), "l"(b), "l"(c))

__device__ __forceinline__ float u2lo(u64 u) { return __uint_as_float((unsigned)(u & 0xffffffffu)); }
__device__ __forceinline__ float u2hi(u64 u) { return __uint_as_float((unsigned)(u >> 32)); }
__device__ __forceinline__ float u2sum(u64 u) { return u2lo(u) + u2hi(u); }

struct F4U { union { float4 f; u64 u[2]; }; };

// warp mma: D(f32 4regs) += A(bf16 4regs) * B(bf16 2regs), m16n8k16
#define MMA16816(d, a, b0, b1) \
    asm volatile("mma.sync.aligned.m16n8k16.row.col.f32.bf16.bf16.f32 " \
        "{%0,%1,%2,%3}, {%4,%5,%6,%7}, {%8,%9}, {%0,%1,%2,%3};" \
        : "+f"((d)[0]), "+f"((d)[1]), "+f"((d)[2]), "+f"((d)[3]) \
        : "r"((a)[0]), "r"((a)[1]), "r"((a)[2]), "r"((a)[3]), "r"(b0), "r"(b1))

__device__ __forceinline__ unsigned pack_bf16x2(float f0, float f1) {
    unsigned r;
    asm("cvt.rn.bf16x2.f32 %0, %1, %2;" : "=r"(r) : "f"(f1), "f"(f0));
    return r;
}

__device__ __forceinline__ void split2(float f0, float f1, unsigned& uh, unsigned& ul) {
    uh = pack_bf16x2(f0, f1);
    float h0 = __uint_as_float(uh << 16);
    float h1 = __uint_as_float(uh & 0xffff0000u);
    ul = pack_bf16x2(f0 - h0, f1 - h1);
}

// ---- scratch (device globals; no allocations allowed) ----
__device__ float g_pose_trans[BND * 12];
__device__ __align__(16) float g_embo[KKEY * EMBD];

__device__ __forceinline__ float lin16(int i) { return -1.0f + (2.0f / 15.0f) * (float)i; }

__device__ __forceinline__ void mat2quat7(const float* m, float* out7) {
    float m00 = m[0], m01 = m[1], m02 = m[2], tx = m[3];
    float m10 = m[4], m11 = m[5], m12 = m[6], ty = m[7];
    float m20 = m[8], m21 = m[9], m22 = m[10], tz = m[11];
    float t, q0, q1, q2, q3;
    if (m22 < 0.0f) {
        if (m00 > m11) {
            t = 1.0f + m00 - m11 - m22;
            q0 = t; q1 = m01 + m10; q2 = m20 + m02; q3 = m12 - m21;
        } else {
            t = 1.0f - m00 + m11 - m22;
            q0 = m01 + m10; q1 = t; q2 = m12 + m21; q3 = m20 - m02;
        }
    } else {
        if (m00 < -m11) {
            t = 1.0f - m00 - m11 + m22;
            q0 = m20 + m02; q1 = m12 + m21; q2 = t; q3 = m01 - m10;
        } else {
            t = 1.0f + m00 + m11 + m22;
            q0 = m12 - m21; q1 = m20 - m02; q2 = m01 - m10; q3 = t;
        }
    }
    float s = 0.5f / sqrtf(t);
    out7[0] = tx; out7[1] = ty; out7[2] = tz;
    out7[3] = q0 * s; out7[4] = q1 * s; out7[5] = q2 * s; out7[6] = q3 * s;
}

// =================== Kernel A: poses (block 0) + key embeddings (blocks 1..32) ===================
__global__ void kA(const float* __restrict__ pose_o, const float* __restrict__ pose_q,
                   const float* __restrict__ Wk1, const float* __restrict__ bk1,
                   const float* __restrict__ Wk2, const float* __restrict__ bk2,
                   float* __restrict__ out_poq, float* __restrict__ out_pqq)
{
    const int t = threadIdx.x;  // 0..255

    if (blockIdx.x == 0) {
        // ---- quats ----
        {
            float q7[7];
            mat2quat7(pose_o + t * 12, q7);
#pragma unroll
            for (int i = 0; i < 7; i++) out_poq[t * 7 + i] = q7[i];
        }
        if (t < BB) {
            float q7[7];
            mat2quat7(pose_q + t * 12, q7);
#pragma unroll
            for (int i = 0; i < 7; i++) out_pqq[t * 7 + i] = q7[i];
        }
        // ---- relative pose: rigid-transform inverse = [R^T | -R^T t] ----
        {
            const float* po = pose_o + t * 12;
            const float* pq = pose_q + (t >> 3) * 12;
            float R[3][3], to[3], Rq[3][3], tq[3];
#pragma unroll
            for (int i = 0; i < 3; i++) {
#pragma unroll
                for (int j = 0; j < 3; j++) { R[i][j] = po[i * 4 + j]; Rq[i][j] = pq[i * 4 + j]; }
                to[i] = po[i * 4 + 3]; tq[i] = pq[i * 4 + 3];
            }
            // out_R = R^T Rq ; out_t = R^T (tq - to)
#pragma unroll
            for (int i = 0; i < 3; i++) {
#pragma unroll
                for (int j = 0; j < 3; j++) {
                    float s = R[0][i] * Rq[0][j];
                    s = fmaf(R[1][i], Rq[1][j], s);
                    s = fmaf(R[2][i], Rq[2][j], s);
                    g_pose_trans[t * 12 + i * 4 + j] = s;
                }
                float s = R[0][i] * (tq[0] - to[0]);
                s = fmaf(R[1][i], tq[1] - to[1], s);
                s = fmaf(R[2][i], tq[2] - to[2], s);
                g_pose_trans[t * 12 + i * 4 + 3] = s;
            }
        }
    } else {
        // ---- key embeddings: one (key, e) pair per thread ----
        const int key = (blockIdx.x - 1) * 8 + (t >> 5);
        const int e   = t & 31;
        const float c0 = lin16(key >> 4), c1 = lin16(key & 15);
        float s = bk2[e];
#pragma unroll 8
        for (int j = 0; j < 128; j++) {
            float h = fmaf(c0, Wk1[j], fmaf(c1, Wk1[128 + j], bk1[j]));
            h = fmaxf(h, 0.0f);
            s = fmaf(h, Wk2[j * EMBD + e], s);
        }
        g_embo[key * EMBD + e] = s;
    }
}

// =================== Kernel B: fused main (256 thr, TQ=64, mma, low-sync) ===================
#define PATT  260   // att [64][260] fp32
#define POUT  66    // epilogue staging [128][66] (att-region union)
#define PV    68    // V half bf16 pitch (words, 128 k values = 64 data words)
#define PBH   132   // hid bf16 pitch (words)
#define PAF   132   // full-row att bf16 pitch (words)
#define PBE   20    // e-dim bf16 fragment pitch (words)

#define OFF_WQ2H  0                           // 4224
#define OFF_WQ2L  4224                        // 4224
#define OFF_EOH   8448                        // 5120
#define OFF_EOL   13568                       // 5120
#define OFF_WA1H  18688                       // 1280
#define OFF_WA1L  19968                       // 1280
#define OFF_ATT   21248                       // 17408: unions att fp32 / out / V-half bf16
#define OFF_TILE  38656                       // 16896: unions hid+eq / att bf16 full-row
#define OFF_BQ2   55552                       // 32
#define OFF_WA2   55584                       // 64
#define OFF_BA1   55648                       // 64
#define OFF_MASKA 55712                       // 64 (half-0 mask partials)
#define OFF_MASKB 55776                       // 64 (half-1 mask partials)
#define OFF_POSE  55840                       // 96
#define OFF_CODE  55936                       // 192
#define SMEM_FLOATS 56128
#define SMEM_BYTES  (SMEM_FLOATS * 4)

extern __shared__ float sm[];

__global__ void __launch_bounds__(NTHR, 1)
kB(const float* __restrict__ vc,
   const float* __restrict__ Wq1, const float* __restrict__ bq1,
   const float* __restrict__ Wq2, const float* __restrict__ bq2,
   const float* __restrict__ Wa1, const float* __restrict__ ba1,
   const float* __restrict__ Wa2, const float* __restrict__ ba2,
   float* __restrict__ dout)
{
    const int t  = threadIdx.x;          // 0..255
    const int qt = blockIdx.x;           // 0..23
    const int b  = blockIdx.y;           // 0..31

    float* sAtt  = sm + OFF_ATT;   // fp32 logits (stage 4 -> softmax)
    float* sOut  = sm + OFF_ATT;   // union (epilogue)
    float* sbq2  = sm + OFF_BQ2;
    float* sWa2  = sm + OFF_WA2;
    float* sba1  = sm + OFF_BA1;
    float* sMWa  = sm + OFF_MASKA;
    float* sMWb  = sm + OFF_MASKB;
    float* sPose = sm + OFF_POSE;
    float* sCode = sm + OFF_CODE;
    unsigned* wq2H = (unsigned*)(sm + OFF_WQ2H);  // [32 e][132] words
    unsigned* wq2L = (unsigned*)(sm + OFF_WQ2L);
    unsigned* eoH  = (unsigned*)(sm + OFF_EOH);   // [256 k][20] words
    unsigned* eoL  = (unsigned*)(sm + OFF_EOL);
    unsigned* wa1H = (unsigned*)(sm + OFF_WA1H);  // [64 j][20] words
    unsigned* wa1L = (unsigned*)(sm + OFF_WA1L);
    unsigned* hidH = (unsigned*)(sm + OFF_TILE);            // [64 q][132]
    unsigned* hidL = (unsigned*)(sm + OFF_TILE + 8448);
    unsigned* eqH  = (unsigned*)(sm + OFF_TILE + 13824);    // [64 q][20]
    unsigned* eqL  = (unsigned*)(sm + OFF_TILE + 15104);
    unsigned* ahiF = (unsigned*)(sm + OFF_TILE);            // [64 q][132] full-row att bf16
    unsigned* aloF = (unsigned*)(sm + OFF_TILE + 8448);
    unsigned* vhiW = (unsigned*)(sm + OFF_ATT);             // [128 c][68] V half bf16
    unsigned* vloW = (unsigned*)(sm + OFF_ATT + 8704);

    // ---- one-time loads / conversions ----
    // Wq2 [256 h][32 e] -> split-bf16 K-major tiles [32 e][128 hpair words]
    {
        const int e = t >> 3;
        const int hp0 = (t & 7) * 16;
#pragma unroll
        for (int i = 0; i < 16; i++) {
            int hp = hp0 + i;
            float f0 = Wq2[(2 * hp) * 32 + e];
            float f1 = Wq2[(2 * hp + 1) * 32 + e];
            unsigned uh, ul;
            split2(f0, f1, uh, ul);
            wq2H[e * PBH + hp] = uh;
            wq2L[e * PBH + hp] = ul;
        }
    }
    // embO [256 k][32 e] fp32 -> split-bf16 [k][16 ewords]
    {
        const float* ep = g_embo + t * 32;
#pragma unroll
        for (int w = 0; w < 16; w++) {
            unsigned uh, ul;
            split2(ep[2 * w], ep[2 * w + 1], uh, ul);
            eoH[t * PBE + w] = uh;
            eoL[t * PBE + w] = ul;
        }
    }
    // Wa1 [32 e][64 j] -> split-bf16 transposed [j][16 ewords]
    if (t < 64) {
#pragma unroll
        for (int w = 0; w < 16; w++) {
            float f0 = Wa1[(2 * w) * 64 + t];
            float f1 = Wa1[(2 * w + 1) * 64 + t];
            unsigned uh, ul;
            split2(f0, f1, uh, ul);
            wa1H[t * PBE + w] = uh;
            wa1L[t * PBE + w] = ul;
        }
    }
    if (t < 64) { sWa2[t] = Wa2[t]; sba1[t] = ba1[t]; }
    if (t < 32) sbq2[t] = bq2[t];
    if (t < 96) sPose[t] = g_pose_trans[b * 96 + t];
    if (t < TQ) {
        int q = qt * TQ + t;
        int d = q >> 8, rm = q & 255;
        sCode[t * 3 + 0] = 0.2f * (float)d;
        sCode[t * 3 + 1] = lin16(rm >> 4);
        sCode[t * 3 + 2] = lin16(rm & 15);
    }

    // stage-1 per-thread weights: two adjacent Wq1 columns (h = 2hp, 2hp+1)
    const int hp   = t & 127;
    const int r0s1 = (t >> 7) * 32;      // rows [r0s1, r0s1+32)
    float wqa[15], wqb[15];
#pragma unroll
    for (int i = 0; i < 15; i++) {
        wqa[i] = Wq1[i * 256 + 2 * hp];
        wqb[i] = Wq1[i * 256 + 2 * hp + 1];
    }
    const float wba = bq1[2 * hp], wbb = bq1[2 * hp + 1];
    const float ba2v = ba2[0];

    // mma tiling: 8 warps = 4 m-tiles x 2 halves
    const int wid = t >> 5, lane = t & 31;
    const int fg  = lane >> 2, fth = lane & 3;       // fragment coords
    const int mrow = (wid >> 1) * 16 + fg;           // q row base
    const int half = wid & 1;
    const int cb   = half * 64;                      // stage-6 c half
    const int nb2  = half * 16;                      // stage-2 e half

    float acc[8][4];
#pragma unroll
    for (int i = 0; i < 8; i++)
#pragma unroll
        for (int j = 0; j < 4; j++) acc[i][j] = 0.0f;

    __syncthreads();

    for (int n = 0; n < NN; n++) {
        const int bn = b * NN + n;
        const float* vcn = vc + (size_t)bn * CELLD * KKEY;

        // ---- stage 1: hidden = relu(inp @ Wq1 + b), written as split-bf16 ----
        {
            const float* ps = &sPose[n * 12];
            float basea = wba, baseb = wbb;
#pragma unroll
            for (int i = 0; i < 12; i++) {
                basea = fmaf(ps[i], wqa[i], basea);
                baseb = fmaf(ps[i], wqb[i], baseb);
            }
#pragma unroll 4
            for (int rr = 0; rr < 32; rr++) {
                const int r = r0s1 + rr;
                float c0 = sCode[r * 3 + 0], c1 = sCode[r * 3 + 1], c2 = sCode[r * 3 + 2];
                float va = basea, vb = baseb;
                va = fmaf(c0, wqa[12], va); vb = fmaf(c0, wqb[12], vb);
                va = fmaf(c1, wqa[13], va); vb = fmaf(c1, wqb[13], vb);
                va = fmaf(c2, wqa[14], va); vb = fmaf(c2, wqb[14], vb);
                va = fmaxf(va, 0.0f); vb = fmaxf(vb, 0.0f);
                unsigned uh, ul;
                split2(va, vb, uh, ul);
                hidH[r * PBH + hp] = uh;
                hidL[r * PBH + hp] = ul;
            }
        }
        __syncthreads();                                        // (1)

        // ---- stage 2 (mma): embq = hid @ Wq2 + b -> split-bf16 fragments ----
        {
            float ea[2][4];
#pragma unroll
            for (int i = 0; i < 2; i++)
#pragma unroll
                for (int j = 0; j < 4; j++) ea[i][j] = 0.0f;
#pragma unroll
            for (int ks = 0; ks < 16; ks++) {
                const int wA = mrow * PBH + ks * 8 + fth;
                unsigned ah[4], al[4];
                ah[0] = hidH[wA];          ah[1] = hidH[wA + 8 * PBH];
                ah[2] = hidH[wA + 4];      ah[3] = hidH[wA + 8 * PBH + 4];
                al[0] = hidL[wA];          al[1] = hidL[wA + 8 * PBH];
                al[2] = hidL[wA + 4];      al[3] = hidL[wA + 8 * PBH + 4];
#pragma unroll
                for (int nt = 0; nt < 2; nt++) {
                    const int wB = (nb2 + nt * 8 + fg) * PBH + ks * 8 + fth;
                    unsigned bh0 = wq2H[wB], bh1 = wq2H[wB + 4];
                    MMA16816(ea[nt], ah, bh0, bh1);
                    MMA16816(ea[nt], al, bh0, bh1);
                    unsigned bl0 = wq2L[wB], bl1 = wq2L[wB + 4];
                    MMA16816(ea[nt], ah, bl0, bl1);
                }
            }
            __syncthreads();                                    // (2) hid reads done
#pragma unroll
            for (int nt = 0; nt < 2; nt++) {
                const int e0 = nb2 + nt * 8 + 2 * fth;
                unsigned uh, ul;
                split2(ea[nt][0] + sbq2[e0], ea[nt][1] + sbq2[e0 + 1], uh, ul);
                eqH[mrow * PBE + (e0 >> 1)] = uh;
                eqL[mrow * PBE + (e0 >> 1)] = ul;
                split2(ea[nt][2] + sbq2[e0], ea[nt][3] + sbq2[e0 + 1], uh, ul);
                eqH[(mrow + 8) * PBE + (e0 >> 1)] = uh;
                eqL[(mrow + 8) * PBE + (e0 >> 1)] = ul;
            }
        }
        __syncthreads();                                        // (3)

        // ---- stage 3 (mma, in-register): mask partials = relu(embq@Wa1+ba1)@Wa2 ----
        {
            const int jb = half * 32;
            float aa[4][4];
#pragma unroll
            for (int i = 0; i < 4; i++)
#pragma unroll
                for (int j = 0; j < 4; j++) aa[i][j] = 0.0f;
#pragma unroll
            for (int kt = 0; kt < 2; kt++) {
                const int wA = mrow * PBE + kt * 8 + fth;
                unsigned ah[4], al[4];
                ah[0] = eqH[wA];          ah[1] = eqH[wA + 8 * PBE];
                ah[2] = eqH[wA + 4];      ah[3] = eqH[wA + 8 * PBE + 4];
                al[0] = eqL[wA];          al[1] = eqL[wA + 8 * PBE];
                al[2] = eqL[wA + 4];      al[3] = eqL[wA + 8 * PBE + 4];
#pragma unroll
                for (int nt = 0; nt < 4; nt++) {
                    const int wB = (jb + nt * 8 + fg) * PBE + kt * 8 + fth;
                    unsigned bh0 = wa1H[wB], bh1 = wa1H[wB + 4];
                    MMA16816(aa[nt], ah, bh0, bh1);
                    MMA16816(aa[nt], al, bh0, bh1);
                    unsigned bl0 = wa1L[wB], bl1 = wa1L[wB + 4];
                    MMA16816(aa[nt], ah, bl0, bl1);
                }
            }
            float p0 = 0.0f, p1 = 0.0f;
#pragma unroll
            for (int nt = 0; nt < 4; nt++) {
                const int j0 = jb + nt * 8 + 2 * fth;
                float w0 = sWa2[j0], w1 = sWa2[j0 + 1];
                float b0 = sba1[j0], b1 = sba1[j0 + 1];
                p0 = fmaf(fmaxf(aa[nt][0] + b0, 0.0f), w0, p0);
                p0 = fmaf(fmaxf(aa[nt][1] + b1, 0.0f), w1, p0);
                p1 = fmaf(fmaxf(aa[nt][2] + b0, 0.0f), w0, p1);
                p1 = fmaf(fmaxf(aa[nt][3] + b1, 0.0f), w1, p1);
            }
            // reduce over fth (quad)
            p0 += __shfl_xor_sync(0xffffffffu, p0, 1);
            p0 += __shfl_xor_sync(0xffffffffu, p0, 2);
            p1 += __shfl_xor_sync(0xffffffffu, p1, 1);
            p1 += __shfl_xor_sync(0xffffffffu, p1, 2);
            if (fth == 0) {
                float* dst = half ? sMWb : sMWa;
                dst[mrow]     = p0;
                dst[mrow + 8] = p1;
            }
        }
        // no sync needed here: stage 4 writes att fp32 (disjoint from eq/mask)

        // ---- stage 4 (mma): logits[64][256] = embq @ emboT ----
        {
            const int n0b = half * 128;
#pragma unroll
            for (int g = 0; g < 2; g++) {
                float lg[8][4];
#pragma unroll
                for (int i = 0; i < 8; i++)
#pragma unroll
                    for (int j = 0; j < 4; j++) lg[i][j] = 0.0f;
#pragma unroll
                for (int kt = 0; kt < 2; kt++) {
                    const int wA = mrow * PBE + kt * 8 + fth;
                    unsigned ah[4], al[4];
                    ah[0] = eqH[wA];          ah[1] = eqH[wA + 8 * PBE];
                    ah[2] = eqH[wA + 4];      ah[3] = eqH[wA + 8 * PBE + 4];
                    al[0] = eqL[wA];          al[1] = eqL[wA + 8 * PBE];
                    al[2] = eqL[wA + 4];      al[3] = eqL[wA + 8 * PBE + 4];
#pragma unroll
                    for (int nt = 0; nt < 8; nt++) {
                        const int wB = (n0b + g * 64 + nt * 8 + fg) * PBE + kt * 8 + fth;
                        unsigned bh0 = eoH[wB], bh1 = eoH[wB + 4];
                        MMA16816(lg[nt], ah, bh0, bh1);
                        MMA16816(lg[nt], al, bh0, bh1);
                        unsigned bl0 = eoL[wB], bl1 = eoL[wB + 4];
                        MMA16816(lg[nt], ah, bl0, bl1);
                    }
                }
#pragma unroll
                for (int nt = 0; nt < 8; nt++) {
                    const int k0 = n0b + g * 64 + nt * 8 + 2 * fth;
                    *(float2*)&sAtt[mrow * PATT + k0]       = make_float2(lg[nt][0], lg[nt][1]);
                    *(float2*)&sAtt[(mrow + 8) * PATT + k0] = make_float2(lg[nt][2], lg[nt][3]);
                }
            }
        }
        __syncthreads();                                        // (4)

        // ---- stage 5 (fused): softmax + mask/sum fold + bf16 conversion ----
        {
#pragma unroll
            for (int rr = 0; rr < 8; rr++) {
                const int r = wid * 8 + rr;
                const float* row = &sAtt[r * PATT + lane * 4];
                float4 a0 = *(const float4*)(row);
                float4 a1 = *(const float4*)(row + 128);
                float mx = fmaxf(fmaxf(fmaxf(a0.x, a0.y), fmaxf(a0.z, a0.w)),
                                 fmaxf(fmaxf(a1.x, a1.y), fmaxf(a1.z, a1.w)));
#pragma unroll
                for (int o = 16; o > 0; o >>= 1) mx = fmaxf(mx, __shfl_xor_sync(0xffffffffu, mx, o));
                float e0 = __expf(a0.x - mx), e1 = __expf(a0.y - mx);
                float e2 = __expf(a0.z - mx), e3 = __expf(a0.w - mx);
                float e4 = __expf(a1.x - mx), e5 = __expf(a1.y - mx);
                float e6 = __expf(a1.z - mx), e7 = __expf(a1.w - mx);
                float s = ((e0 + e1) + (e2 + e3)) + ((e4 + e5) + (e6 + e7));
#pragma unroll
                for (int o = 16; o > 0; o >>= 1) s += __shfl_xor_sync(0xffffffffu, s, o);
                float ml = sMWa[r] + sMWb[r] + ba2v;
                float wr = __fdividef(1.0f, (1.0f + __expf(-ml)) * s);  // sigmoid(ml)/s
                unsigned h0, l0, h1, l1;
                const int w0 = r * PAF + lane * 2;
                split2(e0 * wr, e1 * wr, h0, l0);
                split2(e2 * wr, e3 * wr, h1, l1);
                *(uint2*)&ahiF[w0] = make_uint2(h0, h1);
                *(uint2*)&aloF[w0] = make_uint2(l0, l1);
                split2(e4 * wr, e5 * wr, h0, l0);
                split2(e6 * wr, e7 * wr, h1, l1);
                *(uint2*)&ahiF[w0 + 64] = make_uint2(h0, h1);
                *(uint2*)&aloF[w0 + 64] = make_uint2(l0, l1);
            }
        }
        __syncthreads();                                        // (5)

        // ---- stage 6 (mma): acc += att @ V^T, 2 phases of 128 k each ----
#pragma unroll
        for (int ph = 0; ph < 2; ph++) {
            // convert V k-half [128 c][128 k] -> bf16 hi/lo (clobbers att fp32: dead)
#pragma unroll
            for (int it = 0; it < 16; it++) {
                int id = t + it * 256;
                int c = id >> 5, f = id & 31;
                float4 vv = *(const float4*)(vcn + c * 256 + ph * 128 + f * 4);
                unsigned h0, l0, h1, l1;
                split2(vv.x, vv.y, h0, l0);
                split2(vv.z, vv.w, h1, l1);
                *(uint2*)&vhiW[c * PV + f * 2] = make_uint2(h0, h1);
                *(uint2*)&vloW[c * PV + f * 2] = make_uint2(l0, l1);
            }
            __syncthreads();                                    // (6/8)

#pragma unroll
            for (int kt = 0; kt < 8; kt++) {
                const int wA = mrow * PAF + ph * 64 + kt * 8 + fth;
                unsigned ah[4], al[4];
                ah[0] = ahiF[wA];            ah[1] = ahiF[wA + 8 * PAF];
                ah[2] = ahiF[wA + 4];        ah[3] = ahiF[wA + 8 * PAF + 4];
                al[0] = aloF[wA];            al[1] = aloF[wA + 8 * PAF];
                al[2] = aloF[wA + 4];        al[3] = aloF[wA + 8 * PAF + 4];
                unsigned bh[8][2];
#pragma unroll
                for (int nt = 0; nt < 8; nt++) {
                    const int wB = (cb + nt * 8 + fg) * PV + kt * 8 + fth;
                    bh[nt][0] = vhiW[wB];
                    bh[nt][1] = vhiW[wB + 4];
                    MMA16816(acc[nt], ah, bh[nt][0], bh[nt][1]);
                }
#pragma unroll
                for (int nt = 0; nt < 8; nt++)
                    MMA16816(acc[nt], al, bh[nt][0], bh[nt][1]);
#pragma unroll
                for (int nt = 0; nt < 8; nt++) {
                    const int wB = (cb + nt * 8 + fg) * PV + kt * 8 + fth;
                    unsigned b0 = vloW[wB], b1 = vloW[wB + 4];
                    MMA16816(acc[nt], ah, b0, b1);
                }
            }
            __syncthreads();                                    // (7/9)
        }
    } // n loop

    // ---- epilogue: sigmoid, stage transposed via smem, coalesced store ----
#pragma unroll
    for (int nt = 0; nt < 8; nt++) {
        int c0 = cb + nt * 8 + 2 * fth;
        sOut[c0 * POUT + mrow]           = 1.0f / (1.0f + __expf(-acc[nt][0]));
        sOut[(c0 + 1) * POUT + mrow]     = 1.0f / (1.0f + __expf(-acc[nt][1]));
        sOut[c0 * POUT + mrow + 8]       = 1.0f / (1.0f + __expf(-acc[nt][2]));
        sOut[(c0 + 1) * POUT + mrow + 8] = 1.0f / (1.0f + __expf(-acc[nt][3]));
    }
    __syncthreads();

    float* outp = dout + (size_t)b * CELLD * QQ + qt * TQ;
    for (int id = t; id < CELLD * TQ; id += NTHR) {
        int c = id >> 6, r = id & 63;
        outp[(size_t)c * QQ + r] = sOut[c * POUT + r];
    }
}

// =================== launch ===================
extern "C" void kernel_launch(void* const* d_in, const int* in_sizes, int n_in,
                              void* d_out, int out_size)
{
    (void)in_sizes; (void)n_in; (void)out_size;
    const float* view_cell = (const float*)d_in[0];
    const float* pose_o    = (const float*)d_in[1];
    const float* pose_q    = (const float*)d_in[2];
    const float* Wk1 = (const float*)d_in[3];
    const float* bk1 = (const float*)d_in[4];
    const float* Wk2 = (const float*)d_in[5];
    const float* bk2 = (const float*)d_in[6];
    const float* Wq1 = (const float*)d_in[7];
    const float* bq1 = (const float*)d_in[8];
    const float* Wq2 = (const float*)d_in[9];
    const float* bq2 = (const float*)d_in[10];
    const float* Wa1 = (const float*)d_in[11];
    const float* ba1 = (const float*)d_in[12];
    const float* Wa2 = (const float*)d_in[13];
    const float* ba2 = (const float*)d_in[14];

    float* out = (float*)d_out;
    float* out_poq = out + (size_t)BB * CELLD * QQ;           // [32,8,7]
    float* out_pqq = out_poq + (size_t)BB * NN * 7;           // [32,1,7]

    cudaFuncSetAttribute(kB, cudaFuncAttributeMaxDynamicSharedMemorySize, SMEM_BYTES);

    kA<<<33, 256>>>(pose_o, pose_q, Wk1, bk1, Wk2, bk2, out_poq, out_pqq);
    kB<<<dim3(QQ / TQ, BB), NTHR, SMEM_BYTES>>>(view_cell, Wq1, bq1, Wq2, bq2,
                                                Wa1, ba1, Wa2, ba2, out);
}